// round 3
// baseline (speedup 1.0000x reference)
#include <cuda_runtime.h>
#include <cstdint>

#define HDIM 512
#define NBATCH 4
#define SEQ 4096
#define ATTN_SCALE 0.04419417382415922f  // 512^-0.5

// Scratch (allocation-free rule: __device__ globals)
__device__ float g_Q[(size_t)NBATCH * SEQ * HDIM];          // 32 MB
__device__ float g_S[(size_t)NBATCH * SEQ * SEQ];           // 256 MB

// ---------------------------------------------------------------------------
// GEMM NT: C[m,n] = alpha * sum_k A[m,k] * B[n,k]
// A: [M,K] row-major, B: [N,K] row-major, C: [M,N] row-major.
// Tiles: BM=BN=128, BK=16. 256 threads, 8x8 per thread.
// ---------------------------------------------------------------------------
__global__ __launch_bounds__(256) void gemm_nt(
    const float* __restrict__ A, const float* __restrict__ B,
    float* __restrict__ C, int M, int N, int K,
    long long sA, long long sB, long long sC, float alpha)
{
    __shared__ float As[16][128];
    __shared__ float Bs[16][128];

    const int bz = blockIdx.z;
    A += (long long)bz * sA;
    B += (long long)bz * sB;
    C += (long long)bz * sC;

    const int bm = blockIdx.y * 128;
    const int bn = blockIdx.x * 128;
    const int tid = threadIdx.x;
    const int tx = tid & 15;     // 0..15 -> col group
    const int ty = tid >> 4;     // 0..15 -> row group

    float acc[8][8];
#pragma unroll
    for (int i = 0; i < 8; i++)
#pragma unroll
        for (int j = 0; j < 8; j++) acc[i][j] = 0.0f;

    for (int k0 = 0; k0 < K; k0 += 16) {
        // Load A tile (128x16) and B tile (128x16), both K-major, transpose into smem.
#pragma unroll
        for (int q = 0; q < 2; q++) {
            int idx = tid * 2 + q;         // 0..511 float4 slots
            int row = idx >> 2;            // 0..127
            int cf  = idx & 3;             // float4 within the 16-wide k slab
            float4 va = *(const float4*)(A + (long long)(bm + row) * K + k0 + cf * 4);
            As[cf * 4 + 0][row] = va.x;
            As[cf * 4 + 1][row] = va.y;
            As[cf * 4 + 2][row] = va.z;
            As[cf * 4 + 3][row] = va.w;
            float4 vb = *(const float4*)(B + (long long)(bn + row) * K + k0 + cf * 4);
            Bs[cf * 4 + 0][row] = vb.x;
            Bs[cf * 4 + 1][row] = vb.y;
            Bs[cf * 4 + 2][row] = vb.z;
            Bs[cf * 4 + 3][row] = vb.w;
        }
        __syncthreads();

#pragma unroll
        for (int kk = 0; kk < 16; kk++) {
            float af[8], bf[8];
#pragma unroll
            for (int i = 0; i < 8; i++) af[i] = As[kk][ty * 8 + i];
#pragma unroll
            for (int j = 0; j < 8; j++) bf[j] = Bs[kk][tx * 8 + j];
#pragma unroll
            for (int i = 0; i < 8; i++)
#pragma unroll
                for (int j = 0; j < 8; j++) acc[i][j] = fmaf(af[i], bf[j], acc[i][j]);
        }
        __syncthreads();
    }

#pragma unroll
    for (int i = 0; i < 8; i++) {
        float* crow = C + (long long)(bm + ty * 8 + i) * N + bn + tx * 8;
        float4 o0 = make_float4(acc[i][0] * alpha, acc[i][1] * alpha,
                                acc[i][2] * alpha, acc[i][3] * alpha);
        float4 o1 = make_float4(acc[i][4] * alpha, acc[i][5] * alpha,
                                acc[i][6] * alpha, acc[i][7] * alpha);
        *(float4*)(crow + 0) = o0;
        *(float4*)(crow + 4) = o1;
    }
}

// ---------------------------------------------------------------------------
// GEMM NN: C[m,n] = sum_k A[m,k] * B[k,n]
// A: [M,K] row-major, B: [K,N] row-major, C: [M,N] row-major.
// ---------------------------------------------------------------------------
__global__ __launch_bounds__(256) void gemm_nn(
    const float* __restrict__ A, const float* __restrict__ B,
    float* __restrict__ C, int M, int N, int K,
    long long sA, long long sB, long long sC)
{
    __shared__ float As[16][128];
    __shared__ float Bs[16][128];

    const int bz = blockIdx.z;
    A += (long long)bz * sA;
    B += (long long)bz * sB;
    C += (long long)bz * sC;

    const int bm = blockIdx.y * 128;
    const int bn = blockIdx.x * 128;
    const int tid = threadIdx.x;
    const int tx = tid & 15;
    const int ty = tid >> 4;

    float acc[8][8];
#pragma unroll
    for (int i = 0; i < 8; i++)
#pragma unroll
        for (int j = 0; j < 8; j++) acc[i][j] = 0.0f;

    for (int k0 = 0; k0 < K; k0 += 16) {
#pragma unroll
        for (int q = 0; q < 2; q++) {
            int idx = tid * 2 + q;         // 0..511
            // A tile: 128 rows x 16 k, transpose in
            int arow = idx >> 2;
            int acf  = idx & 3;
            float4 va = *(const float4*)(A + (long long)(bm + arow) * K + k0 + acf * 4);
            As[acf * 4 + 0][arow] = va.x;
            As[acf * 4 + 1][arow] = va.y;
            As[acf * 4 + 2][arow] = va.z;
            As[acf * 4 + 3][arow] = va.w;
            // B tile: 16 k-rows x 128 n, direct
            int krow = idx >> 5;           // 0..15
            int nf   = idx & 31;           // 0..31 float4 across 128
            float4 vb = *(const float4*)(B + (long long)(k0 + krow) * N + bn + nf * 4);
            *(float4*)&Bs[krow][nf * 4] = vb;
        }
        __syncthreads();

#pragma unroll
        for (int kk = 0; kk < 16; kk++) {
            float af[8], bf[8];
#pragma unroll
            for (int i = 0; i < 8; i++) af[i] = As[kk][ty * 8 + i];
#pragma unroll
            for (int j = 0; j < 8; j++) bf[j] = Bs[kk][tx * 8 + j];
#pragma unroll
            for (int i = 0; i < 8; i++)
#pragma unroll
                for (int j = 0; j < 8; j++) acc[i][j] = fmaf(af[i], bf[j], acc[i][j]);
        }
        __syncthreads();
    }

#pragma unroll
    for (int i = 0; i < 8; i++) {
        float* crow = C + (long long)(bm + ty * 8 + i) * N + bn + tx * 8;
        *(float4*)(crow + 0) = make_float4(acc[i][0], acc[i][1], acc[i][2], acc[i][3]);
        *(float4*)(crow + 4) = make_float4(acc[i][4], acc[i][5], acc[i][6], acc[i][7]);
    }
}

// ---------------------------------------------------------------------------
// Row softmax over SEQ=4096 columns, one block (256 threads) per row.
// ---------------------------------------------------------------------------
__global__ __launch_bounds__(256) void softmax_rows(float* __restrict__ S)
{
    const size_t row = blockIdx.x;
    float4* p4 = (float4*)(S + row * SEQ);
    const int tid = threadIdx.x;

    float v[16];
    float m = -1e30f;
#pragma unroll
    for (int q = 0; q < 4; q++) {
        float4 t = p4[tid + q * 256];
        v[q * 4 + 0] = t.x; v[q * 4 + 1] = t.y;
        v[q * 4 + 2] = t.z; v[q * 4 + 3] = t.w;
        m = fmaxf(m, fmaxf(fmaxf(t.x, t.y), fmaxf(t.z, t.w)));
    }

    __shared__ float red[8];
    __shared__ float s_bcast;
#pragma unroll
    for (int o = 16; o > 0; o >>= 1) m = fmaxf(m, __shfl_xor_sync(0xffffffffu, m, o));
    if ((tid & 31) == 0) red[tid >> 5] = m;
    __syncthreads();
    if (tid == 0) {
        float mm = red[0];
#pragma unroll
        for (int i = 1; i < 8; i++) mm = fmaxf(mm, red[i]);
        s_bcast = mm;
    }
    __syncthreads();
    m = s_bcast;

    float sum = 0.0f;
#pragma unroll
    for (int i = 0; i < 16; i++) {
        v[i] = __expf(v[i] - m);
        sum += v[i];
    }
#pragma unroll
    for (int o = 16; o > 0; o >>= 1) sum += __shfl_xor_sync(0xffffffffu, sum, o);
    __syncthreads();            // protect red[] reuse
    if ((tid & 31) == 0) red[tid >> 5] = sum;
    __syncthreads();
    if (tid == 0) {
        float ss = 0.0f;
#pragma unroll
        for (int i = 0; i < 8; i++) ss += red[i];
        s_bcast = 1.0f / ss;
    }
    __syncthreads();
    const float inv = s_bcast;

#pragma unroll
    for (int q = 0; q < 4; q++) {
        float4 t = make_float4(v[q * 4 + 0] * inv, v[q * 4 + 1] * inv,
                               v[q * 4 + 2] * inv, v[q * 4 + 3] * inv);
        p4[tid + q * 256] = t;
    }
}

// ---------------------------------------------------------------------------
// Launch
// ---------------------------------------------------------------------------
extern "C" void kernel_launch(void* const* d_in, const int* in_sizes, int n_in,
                              void* d_out, int out_size)
{
    const float* x  = (const float*)d_in[0];   // [4, 4096, 512]
    const float* Wq = (const float*)d_in[1];   // [512, 512]  (torch layout [out,in])
    float* y = (float*)d_out;                  // [4, 4096, 512]

    float *Qp = nullptr, *Sp = nullptr;
    cudaGetSymbolAddress((void**)&Qp, g_Q);
    cudaGetSymbolAddress((void**)&Sp, g_S);

    const long long qStride = (long long)SEQ * HDIM;     // per-batch Q/Y stride
    const long long sStride = (long long)SEQ * SEQ;      // per-batch S stride

    // 1) Q = X @ Wq^T   (M=16384, N=512, K=512)
    {
        dim3 grid(HDIM / 128, (NBATCH * SEQ) / 128, 1);
        gemm_nt<<<grid, 256>>>(x, Wq, Qp,
                               NBATCH * SEQ, HDIM, HDIM,
                               0LL, 0LL, 0LL, 1.0f);
    }
    // 2) S_b = scale * Q_b @ Q_b^T  (M=N=4096, K=512, batched over z)
    {
        dim3 grid(SEQ / 128, SEQ / 128, NBATCH);
        gemm_nt<<<grid, 256>>>(Qp, Qp, Sp,
                               SEQ, SEQ, HDIM,
                               qStride, qStride, sStride, ATTN_SCALE);
    }
    // 3) row softmax over all NBATCH*SEQ rows
    softmax_rows<<<NBATCH * SEQ, 256>>>(Sp);

    // 4) Y_b = P_b @ Q_b  (M=4096, N=512, K=4096, batched)
    {
        dim3 grid(HDIM / 128, SEQ / 128, NBATCH);
        gemm_nn<<<grid, 256>>>(Sp, Qp, y,
                               SEQ, HDIM, SEQ,
                               sStride, qStride, qStride);
    }
}

// round 8
// speedup vs baseline: 2.7107x; 2.7107x over previous
#include <cuda_runtime.h>
#include <cuda_bf16.h>
#include <cstdint>
#include <cstddef>

#define HDIM 512
#define NBATCH 4
#define SEQ 4096
#define ATTN_SCALE 0.04419417382415922f  // 512^-0.5

// ---------------------------------------------------------------------------
// Scratch (allocation-free rule: __device__ globals)
// ---------------------------------------------------------------------------
__device__ float g_Qf[(size_t)NBATCH * SEQ * HDIM];
__device__ float g_S [(size_t)NBATCH * SEQ * SEQ];
__device__ __nv_bfloat16 g_Xh[(size_t)NBATCH * SEQ * HDIM];
__device__ __nv_bfloat16 g_Xl[(size_t)NBATCH * SEQ * HDIM];
__device__ __nv_bfloat16 g_Wh[(size_t)HDIM * HDIM];
__device__ __nv_bfloat16 g_Wl[(size_t)HDIM * HDIM];
__device__ __nv_bfloat16 g_Qh[(size_t)NBATCH * SEQ * HDIM];
__device__ __nv_bfloat16 g_Ql[(size_t)NBATCH * SEQ * HDIM];
__device__ __nv_bfloat16 g_QTh[(size_t)NBATCH * HDIM * SEQ];
__device__ __nv_bfloat16 g_QTl[(size_t)NBATCH * HDIM * SEQ];
__device__ __nv_bfloat16 g_Ph[(size_t)NBATCH * SEQ * SEQ];
__device__ __nv_bfloat16 g_Pl[(size_t)NBATCH * SEQ * SEQ];

// ---------------------------------------------------------------------------
// Helpers
// ---------------------------------------------------------------------------
__device__ __forceinline__ uint32_t smem_to_u32(const void* p) {
    uint32_t a;
    asm("{ .reg .u64 t; cvta.to.shared.u64 t, %1; cvt.u32.u64 %0, t; }"
        : "=r"(a) : "l"(p));
    return a;
}

__device__ __forceinline__ void cp16(uint32_t dst, const __nv_bfloat16* src) {
    asm volatile("cp.async.cg.shared.global [%0], [%1], 16;"
                 :: "r"(dst), "l"(__cvta_generic_to_global(src)));
}
#define CP_COMMIT() asm volatile("cp.async.commit_group;" ::: "memory")
#define CP_WAIT1()  asm volatile("cp.async.wait_group 1;" ::: "memory")

#define LDSM4(r, addr) \
    asm volatile("ldmatrix.sync.aligned.m8n8.x4.shared.b16 {%0,%1,%2,%3}, [%4];" \
        : "=r"((r)[0]), "=r"((r)[1]), "=r"((r)[2]), "=r"((r)[3]) : "r"(addr))

#define MMA16816(d, a, b0, b1) \
    asm volatile("mma.sync.aligned.m16n8k16.row.col.f32.bf16.bf16.f32 " \
        "{%0,%1,%2,%3}, {%4,%5,%6,%7}, {%8,%9}, {%0,%1,%2,%3};" \
        : "+f"((d)[0]), "+f"((d)[1]), "+f"((d)[2]), "+f"((d)[3]) \
        : "r"((a)[0]), "r"((a)[1]), "r"((a)[2]), "r"((a)[3]), "r"(b0), "r"(b1))

// ---------------------------------------------------------------------------
// Split-bf16 NT GEMM via mma.sync (HMMA):
//   C[m,n] = alpha * sum_k (Ah+Al)[m,k]*(Bh+Bl)[n,k]
//   ~= alpha * (Ah*Bh + Al*Bh + Ah*Bl)
// Block 128x128, BK=32, 8 warps (2x4), warp tile 64x32, cp.async 2 stages.
// SMEM row stride = 40 bf16 (80B): pad-8 -> conflict-free ldmatrix.
// ---------------------------------------------------------------------------
#define ROWB   80u       // bytes per smem tile row (32 bf16 + 8 pad)
#define TILEB  10240u    // 128 rows * 80B
#define STAGEB 40960u    // Ah | Al | Bh | Bl
#define GM_SMEM (2u * STAGEB)

__global__ __launch_bounds__(256, 1)
void gemm_nt_mma(const __nv_bfloat16* __restrict__ Ah, const __nv_bfloat16* __restrict__ Al,
                 const __nv_bfloat16* __restrict__ Bh, const __nv_bfloat16* __restrict__ Bl,
                 float* __restrict__ C, int M, int N, int K,
                 long long bsA, long long bsB, long long bsC, float alpha)
{
    extern __shared__ char smem[];
    const uint32_t su = smem_to_u32(smem);
    const int tid  = threadIdx.x;
    const int wid  = tid >> 5;
    const int lane = tid & 31;
    const int wm = wid >> 2;          // 0..1 -> m offset 0/64
    const int wn = wid & 3;           // 0..3 -> n offset 0/32/64/96
    const int bz = blockIdx.z;
    const int bm = blockIdx.y * 128;
    const int bn = blockIdx.x * 128;

    const __nv_bfloat16* gAh = Ah + (size_t)bz * bsA;
    const __nv_bfloat16* gAl = Al + (size_t)bz * bsA;
    const __nv_bfloat16* gBh = Bh + (size_t)bz * bsB;
    const __nv_bfloat16* gBl = Bl + (size_t)bz * bsB;

    float acc[4][4][4];
#pragma unroll
    for (int i = 0; i < 4; i++)
#pragma unroll
        for (int j = 0; j < 4; j++)
#pragma unroll
            for (int r = 0; r < 4; r++) acc[i][j][r] = 0.0f;

    // loader: one BK=32 chunk (4 tiles) into stage base sb
    auto load_stage = [&](int k0, uint32_t sb) {
#pragma unroll
        for (int t = 0; t < 8; t++) {
            int c    = tid + t * 256;        // 0..2047
            int tile = c >> 9;               // 0..3 : Ah, Al, Bh, Bl
            int r    = (c >> 2) & 127;
            int col  = c & 3;                // 16B chunk within row
            uint32_t so = sb + (uint32_t)tile * TILEB + (uint32_t)r * ROWB + (uint32_t)col * 16u;
            const __nv_bfloat16* src;
            if (tile == 0)      src = gAh + (size_t)(bm + r) * K + k0 + col * 8;
            else if (tile == 1) src = gAl + (size_t)(bm + r) * K + k0 + col * 8;
            else if (tile == 2) src = gBh + (size_t)(bn + r) * K + k0 + col * 8;
            else                src = gBl + (size_t)(bn + r) * K + k0 + col * 8;
            cp16(so, src);
        }
    };

    // per-lane ldmatrix address pieces
    const uint32_t aRow = (uint32_t)(lane & 15);
    const uint32_t aC8  = (uint32_t)((lane >> 4) << 3);
    const uint32_t bRow = (uint32_t)((lane & 7) + ((lane >> 4) << 3));
    const uint32_t bC8  = (uint32_t)(((lane >> 3) & 1) << 3);
    const uint32_t aBase = (uint32_t)(wm * 64 + aRow) * ROWB + aC8 * 2u;
    const uint32_t bBase = (uint32_t)(wn * 32 + bRow) * ROWB + bC8 * 2u;

    const int nc = K >> 5;

    load_stage(0, su);            CP_COMMIT();
    load_stage(32, su + STAGEB);  CP_COMMIT();

    for (int i = 0; i < nc; i++) {
        const uint32_t sb = su + (uint32_t)(i & 1) * STAGEB;
        CP_WAIT1();
        __syncthreads();

        const uint32_t tAh = sb, tAl = sb + TILEB, tBh = sb + 2u * TILEB, tBl = sb + 3u * TILEB;
#pragma unroll
        for (int ks = 0; ks < 2; ks++) {
            uint32_t ah[4][4], al[4][4], bh[2][4], bl[2][4];
#pragma unroll
            for (int mf = 0; mf < 4; mf++) {
                uint32_t off = aBase + (uint32_t)(mf * 16) * ROWB + (uint32_t)(ks * 32);
                LDSM4(ah[mf], tAh + off);
                LDSM4(al[mf], tAl + off);
            }
#pragma unroll
            for (int nf2 = 0; nf2 < 2; nf2++) {
                uint32_t off = bBase + (uint32_t)(nf2 * 16) * ROWB + (uint32_t)(ks * 32);
                LDSM4(bh[nf2], tBh + off);
                LDSM4(bl[nf2], tBl + off);
            }
#pragma unroll
            for (int mf = 0; mf < 4; mf++)
#pragma unroll
                for (int nf = 0; nf < 4; nf++) {
                    uint32_t* bph = &bh[nf >> 1][(nf & 1) * 2];
                    uint32_t* bpl = &bl[nf >> 1][(nf & 1) * 2];
                    MMA16816(acc[mf][nf], ah[mf], bph[0], bph[1]);
                    MMA16816(acc[mf][nf], al[mf], bph[0], bph[1]);
                    MMA16816(acc[mf][nf], ah[mf], bpl[0], bpl[1]);
                }
        }

        __syncthreads();
        if (i + 2 < nc) load_stage((i + 2) << 5, sb);
        CP_COMMIT();
    }

    // epilogue
    float* Cb = C + (size_t)bz * bsC;
#pragma unroll
    for (int mf = 0; mf < 4; mf++) {
        int r0 = bm + wm * 64 + mf * 16 + (lane >> 2);
#pragma unroll
        for (int nf = 0; nf < 4; nf++) {
            int c0 = bn + wn * 32 + nf * 8 + (lane & 3) * 2;
            float2 v0 = make_float2(acc[mf][nf][0] * alpha, acc[mf][nf][1] * alpha);
            float2 v1 = make_float2(acc[mf][nf][2] * alpha, acc[mf][nf][3] * alpha);
            *(float2*)(Cb + (size_t)r0 * N + c0)       = v0;
            *(float2*)(Cb + (size_t)(r0 + 8) * N + c0) = v1;
        }
    }
}

// ---------------------------------------------------------------------------
// fp32 -> (hi, lo) bf16 split, 4 elems/thread
// ---------------------------------------------------------------------------
__global__ __launch_bounds__(256) void split_hl(
    const float* __restrict__ in, __nv_bfloat16* __restrict__ h,
    __nv_bfloat16* __restrict__ l, size_t n)
{
    size_t i = ((size_t)blockIdx.x * 256 + threadIdx.x) * 4;
    if (i >= n) return;
    float4 v = *(const float4*)(in + i);
    __nv_bfloat16 h0 = __float2bfloat16(v.x), h1 = __float2bfloat16(v.y);
    __nv_bfloat16 h2 = __float2bfloat16(v.z), h3 = __float2bfloat16(v.w);
    __nv_bfloat16 l0 = __float2bfloat16(v.x - __bfloat162float(h0));
    __nv_bfloat16 l1 = __float2bfloat16(v.y - __bfloat162float(h1));
    __nv_bfloat16 l2 = __float2bfloat16(v.z - __bfloat162float(h2));
    __nv_bfloat16 l3 = __float2bfloat16(v.w - __bfloat162float(h3));
    *(__nv_bfloat162*)(h + i)     = __halves2bfloat162(h0, h1);
    *(__nv_bfloat162*)(h + i + 2) = __halves2bfloat162(h2, h3);
    *(__nv_bfloat162*)(l + i)     = __halves2bfloat162(l0, l1);
    *(__nv_bfloat162*)(l + i + 2) = __halves2bfloat162(l2, l3);
}

// ---------------------------------------------------------------------------
// Q [b][SEQ, HDIM] fp32 -> QT hi/lo [b][HDIM, SEQ] bf16 (transpose + split)
// ---------------------------------------------------------------------------
__global__ __launch_bounds__(256) void transpose_split(
    const float* __restrict__ Q, __nv_bfloat16* __restrict__ th,
    __nv_bfloat16* __restrict__ tl)
{
    __shared__ float tile[32][33];
    const int b = blockIdx.z;
    const int d0 = blockIdx.x * 32;
    const int r0 = blockIdx.y * 32;
    const int tx = threadIdx.x & 31, ty = threadIdx.x >> 5;
    const float* Qb = Q + (size_t)b * SEQ * HDIM;
#pragma unroll
    for (int rr = ty; rr < 32; rr += 8)
        tile[rr][tx] = Qb[(size_t)(r0 + rr) * HDIM + d0 + tx];
    __syncthreads();
    __nv_bfloat16* thb = th + (size_t)b * HDIM * SEQ;
    __nv_bfloat16* tlb = tl + (size_t)b * HDIM * SEQ;
#pragma unroll
    for (int cc = ty; cc < 32; cc += 8) {
        float v = tile[tx][cc];
        __nv_bfloat16 hh = __float2bfloat16(v);
        __nv_bfloat16 ll = __float2bfloat16(v - __bfloat162float(hh));
        thb[(size_t)(d0 + cc) * SEQ + r0 + tx] = hh;
        tlb[(size_t)(d0 + cc) * SEQ + r0 + tx] = ll;
    }
}

// ---------------------------------------------------------------------------
// Row softmax over SEQ cols, fused with (hi, lo) bf16 output.
// ---------------------------------------------------------------------------
__global__ __launch_bounds__(256) void softmax_split(
    const float* __restrict__ S, __nv_bfloat16* __restrict__ Ph,
    __nv_bfloat16* __restrict__ Pl)
{
    const size_t row = blockIdx.x;
    const float4* p4 = (const float4*)(S + row * SEQ);
    const int tid = threadIdx.x;

    float v[16];
    float m = -1e30f;
#pragma unroll
    for (int q = 0; q < 4; q++) {
        float4 t = p4[tid + q * 256];
        v[q * 4 + 0] = t.x; v[q * 4 + 1] = t.y;
        v[q * 4 + 2] = t.z; v[q * 4 + 3] = t.w;
        m = fmaxf(m, fmaxf(fmaxf(t.x, t.y), fmaxf(t.z, t.w)));
    }

    __shared__ float red[8];
    __shared__ float s_bcast;
#pragma unroll
    for (int o = 16; o > 0; o >>= 1) m = fmaxf(m, __shfl_xor_sync(0xffffffffu, m, o));
    if ((tid & 31) == 0) red[tid >> 5] = m;
    __syncthreads();
    if (tid == 0) {
        float mm = red[0];
#pragma unroll
        for (int i = 1; i < 8; i++) mm = fmaxf(mm, red[i]);
        s_bcast = mm;
    }
    __syncthreads();
    m = s_bcast;

    float sum = 0.0f;
#pragma unroll
    for (int i = 0; i < 16; i++) { v[i] = __expf(v[i] - m); sum += v[i]; }
#pragma unroll
    for (int o = 16; o > 0; o >>= 1) sum += __shfl_xor_sync(0xffffffffu, sum, o);
    __syncthreads();
    if ((tid & 31) == 0) red[tid >> 5] = sum;
    __syncthreads();
    if (tid == 0) {
        float ss = 0.0f;
#pragma unroll
        for (int i = 0; i < 8; i++) ss += red[i];
        s_bcast = 1.0f / ss;
    }
    __syncthreads();
    const float inv = s_bcast;

    __nv_bfloat16* phr = Ph + row * SEQ;
    __nv_bfloat16* plr = Pl + row * SEQ;
#pragma unroll
    for (int q = 0; q < 4; q++) {
        int e = (tid + q * 256) * 4;
        float p0 = v[q * 4 + 0] * inv, p1 = v[q * 4 + 1] * inv;
        float p2 = v[q * 4 + 2] * inv, p3 = v[q * 4 + 3] * inv;
        __nv_bfloat16 h0 = __float2bfloat16(p0), h1 = __float2bfloat16(p1);
        __nv_bfloat16 h2 = __float2bfloat16(p2), h3 = __float2bfloat16(p3);
        __nv_bfloat16 l0 = __float2bfloat16(p0 - __bfloat162float(h0));
        __nv_bfloat16 l1 = __float2bfloat16(p1 - __bfloat162float(h1));
        __nv_bfloat16 l2 = __float2bfloat16(p2 - __bfloat162float(h2));
        __nv_bfloat16 l3 = __float2bfloat16(p3 - __bfloat162float(h3));
        *(__nv_bfloat162*)(phr + e)     = __halves2bfloat162(h0, h1);
        *(__nv_bfloat162*)(phr + e + 2) = __halves2bfloat162(h2, h3);
        *(__nv_bfloat162*)(plr + e)     = __halves2bfloat162(l0, l1);
        *(__nv_bfloat162*)(plr + e + 2) = __halves2bfloat162(l2, l3);
    }
}

// ---------------------------------------------------------------------------
// Launch
// ---------------------------------------------------------------------------
extern "C" void kernel_launch(void* const* d_in, const int* in_sizes, int n_in,
                              void* d_out, int out_size)
{
    const float* x  = (const float*)d_in[0];   // [4, 4096, 512]
    const float* Wq = (const float*)d_in[1];   // [512, 512]
    float* y = (float*)d_out;                  // [4, 4096, 512]

    float *Qf, *S;
    __nv_bfloat16 *Xh, *Xl, *Wh, *Wl, *Qh, *Ql, *QTh, *QTl, *Ph, *Pl;
    cudaGetSymbolAddress((void**)&Qf,  g_Qf);
    cudaGetSymbolAddress((void**)&S,   g_S);
    cudaGetSymbolAddress((void**)&Xh,  g_Xh);
    cudaGetSymbolAddress((void**)&Xl,  g_Xl);
    cudaGetSymbolAddress((void**)&Wh,  g_Wh);
    cudaGetSymbolAddress((void**)&Wl,  g_Wl);
    cudaGetSymbolAddress((void**)&Qh,  g_Qh);
    cudaGetSymbolAddress((void**)&Ql,  g_Ql);
    cudaGetSymbolAddress((void**)&QTh, g_QTh);
    cudaGetSymbolAddress((void**)&QTl, g_QTl);
    cudaGetSymbolAddress((void**)&Ph,  g_Ph);
    cudaGetSymbolAddress((void**)&Pl,  g_Pl);

    cudaFuncSetAttribute(gemm_nt_mma, cudaFuncAttributeMaxDynamicSharedMemorySize, GM_SMEM);

    const size_t nX = (size_t)NBATCH * SEQ * HDIM;
    const size_t nW = (size_t)HDIM * HDIM;
    const long long qStride = (long long)SEQ * HDIM;
    const long long sStride = (long long)SEQ * SEQ;
    const long long tStride = (long long)HDIM * SEQ;

    // 0) split inputs
    split_hl<<<(unsigned)(nX / 1024), 256>>>(x, Xh, Xl, nX);
    split_hl<<<(unsigned)(nW / 1024), 256>>>(Wq, Wh, Wl, nW);

    // 1) Q = X @ Wq^T   (M=16384, N=512, K=512)
    {
        dim3 grid(HDIM / 128, (NBATCH * SEQ) / 128, 1);
        gemm_nt_mma<<<grid, 256, GM_SMEM>>>(Xh, Xl, Wh, Wl, Qf,
                                            NBATCH * SEQ, HDIM, HDIM,
                                            0LL, 0LL, 0LL, 1.0f);
    }

    // 2) split Q; transpose-split Q -> QT
    split_hl<<<(unsigned)(nX / 1024), 256>>>(Qf, Qh, Ql, nX);
    {
        dim3 grid(HDIM / 32, SEQ / 32, NBATCH);
        transpose_split<<<grid, 256>>>(Qf, QTh, QTl);
    }

    // 3) S_b = scale * Q_b @ Q_b^T  (M=N=4096, K=512)
    {
        dim3 grid(SEQ / 128, SEQ / 128, NBATCH);
        gemm_nt_mma<<<grid, 256, GM_SMEM>>>(Qh, Ql, Qh, Ql, S,
                                            SEQ, SEQ, HDIM,
                                            qStride, qStride, sStride, ATTN_SCALE);
    }

    // 4) softmax rows -> P hi/lo
    softmax_split<<<NBATCH * SEQ, 256>>>(S, Ph, Pl);

    // 5) Y_b = P_b @ Q_b = P_b @ (QT_b)^T  (M=4096, N=512, K=4096)
    {
        dim3 grid(HDIM / 128, SEQ / 128, NBATCH);
        gemm_nt_mma<<<grid, 256, GM_SMEM>>>(Ph, Pl, QTh, QTl, y,
                                            sStride ? SEQ : SEQ, HDIM, SEQ,
                                            sStride, tStride, qStride, 1.0f);
    }
}